// round 16
// baseline (speedup 1.0000x reference)
#include <cuda_runtime.h>
#include <cuda_bf16.h>
#include <cstdint>

#define NROWS 16384
#define KDIM  4096
#define ODIM  4096

// Arch-feature guard: tcgen05 only exists in arch-specific ('a') / family targets.
#if defined(__CUDA_ARCH_FEAT_SM103_ALL) || defined(__CUDA_ARCH_FEAT_SM100_ALL) || \
    defined(__CUDA_ARCH_SPECIFIC__) || defined(__CUDA_ARCH_FAMILY_SPECIFIC__)
#define HAS_TCGEN05 1
#else
#define HAS_TCGEN05 0
#endif

// ---------------- scratch: TILED-SWIZZLED bf16 operands ----------------
// Block (tile, kstage) = 32 KB contiguous: 256 rows x 128B, each row SW128-swizzled
// (16B chunk cc at offset (cc ^ (row&7))*16). A stage is one contiguous 32KB block.
__device__ unsigned char g_qxt[(size_t)NROWS * KDIM * 2];   // 128 MB
__device__ unsigned char g_qwt[(size_t)ODIM * KDIM * 2];    // 32 MB
__device__ float g_wscale[ODIM];
// Zero-invariant state: zero at module load; every kernel_launch execution
// restores them to zero (params1 resets r-minmax, params2 resets x-minmax).
__device__ unsigned int g_xmax_u, g_xmin_u, g_rmax_u, g_rmin_u;
__device__ float g_sc, g_zp, g_resc, g_rezp;

// ---------------- PTX helpers ----------------
__device__ __forceinline__ uint32_t smem_u32(const void* p) {
    uint32_t a;
    asm("{ .reg .u64 t; cvta.to.shared.u64 t, %1; cvt.u32.u64 %0, t; }" : "=r"(a) : "l"(p));
    return a;
}
#define TCGEN05_ALLOC(sm, n) \
    asm volatile("tcgen05.alloc.cta_group::1.sync.aligned.shared::cta.b32 [%0], %1;" \
                 :: "r"((uint32_t)(sm)), "r"((uint32_t)(n)) : "memory")
#define TCGEN05_DEALLOC(t, n) \
    asm volatile("tcgen05.dealloc.cta_group::1.sync.aligned.b32 %0, %1;" :: "r"(t), "r"((uint32_t)(n)))
#define TCGEN05_RELINQ() \
    asm volatile("tcgen05.relinquish_alloc_permit.cta_group::1.sync.aligned;")
#define TCGEN05_COMMIT(mb) \
    asm volatile("tcgen05.commit.cta_group::1.mbarrier::arrive::one.shared::cluster.b64 [%0];" \
                 :: "r"((uint32_t)(mb)) : "memory")
#define TCGEN05_FENCE_AFTER()  asm volatile("tcgen05.fence::after_thread_sync;" ::: "memory")
#define TCGEN05_FENCE_BEFORE() asm volatile("tcgen05.fence::before_thread_sync;" ::: "memory")
#define TCGEN05_WAIT_LD()      asm volatile("tcgen05.wait::ld.sync.aligned;" ::: "memory")
#define MBAR_INIT(a, c) \
    asm volatile("mbarrier.init.shared.b64 [%0], %1;" :: "r"((uint32_t)(a)), "r"((uint32_t)(c)) : "memory")
#define FENCE_PROXY_ASYNC() asm volatile("fence.proxy.async.shared::cta;" ::: "memory")

#define MBAR_WAIT_PARITY(mb, par) do {                                            \
    uint32_t _m = (uint32_t)(mb); uint32_t _p = (uint32_t)(par);                  \
    asm volatile(                                                                 \
        "{\n\t.reg .pred P1;\n\t"                                                 \
        "WL_%=:\n\t"                                                              \
        "mbarrier.try_wait.parity.acquire.cta.shared::cta.b64 P1, [%0], %1, 0x989680;\n\t" \
        "@P1 bra.uni WD_%=;\n\t"                                                  \
        "bra.uni WL_%=;\n\t"                                                      \
        "WD_%=:\n\t}"                                                             \
        :: "r"(_m), "r"(_p) : "memory");                                          \
} while (0)

#define TCGEN05_LD_X32(r, addr) \
    asm volatile( \
        "tcgen05.ld.sync.aligned.32x32b.x32.b32 " \
        "{%0, %1, %2, %3, %4, %5, %6, %7, " \
        " %8, %9, %10, %11, %12, %13, %14, %15, " \
        " %16, %17, %18, %19, %20, %21, %22, %23, " \
        " %24, %25, %26, %27, %28, %29, %30, %31}, [%32];" \
        : "=r"((r)[0]),  "=r"((r)[1]),  "=r"((r)[2]),  "=r"((r)[3]), \
          "=r"((r)[4]),  "=r"((r)[5]),  "=r"((r)[6]),  "=r"((r)[7]), \
          "=r"((r)[8]),  "=r"((r)[9]),  "=r"((r)[10]), "=r"((r)[11]), \
          "=r"((r)[12]), "=r"((r)[13]), "=r"((r)[14]), "=r"((r)[15]), \
          "=r"((r)[16]), "=r"((r)[17]), "=r"((r)[18]), "=r"((r)[19]), \
          "=r"((r)[20]), "=r"((r)[21]), "=r"((r)[22]), "=r"((r)[23]), \
          "=r"((r)[24]), "=r"((r)[25]), "=r"((r)[26]), "=r"((r)[27]), \
          "=r"((r)[28]), "=r"((r)[29]), "=r"((r)[30]), "=r"((r)[31]) \
        : "r"(addr))

__device__ __forceinline__ void cp16(uint32_t s, const void* g) {
    asm volatile("cp.async.cg.shared.global [%0], [%1], 16;" :: "r"(s), "l"(g));
}
#define CP_COMMIT() asm volatile("cp.async.commit_group;" ::: "memory")
#define CP_WAIT1()  asm volatile("cp.async.wait_group 1;" ::: "memory")

// SW128 K-major descriptor (layout=2, version=1, SBO=64, LBO=1) — 128B rows
__device__ __forceinline__ uint64_t make_desc(uint32_t addr) {
    return ((uint64_t)2 << 61) | ((uint64_t)1 << 46) | ((uint64_t)64 << 32) |
           ((uint64_t)1 << 16) | ((addr >> 4) & 0x3FFF);
}

// idesc kind::f16: dtype=F32(bit4), atype=BF16(bit7), btype=BF16(bit10), N=256, M=128
#define GEMM_IDESC ((1u << 4) | (1u << 7) | (1u << 10) | ((256u / 8) << 17) | ((128u / 16) << 24))

__device__ __forceinline__ void mma_f16_ss(uint32_t d, uint64_t ad, uint64_t bd,
                                           uint32_t idesc, bool acc) {
    uint32_t e = acc ? 1u : 0u;
    asm volatile(
        "{\n\t.reg .pred p;\n\t"
        "setp.ne.u32 p, %4, 0;\n\t"
        "tcgen05.mma.cta_group::1.kind::f16 [%0], %1, %2, %3, {%5,%5,%5,%5}, p;\n\t"
        "}"
        :: "r"(d), "l"(ad), "l"(bd), "r"(idesc), "r"(e), "r"(0u) : "memory");
}

// ---------------- misc kernels ----------------
__device__ __forceinline__ void block_minmax_atomic(float tmn, float tmx,
                                                    unsigned int* gmin, unsigned int* gmax) {
    #pragma unroll
    for (int o = 16; o > 0; o >>= 1) {
        tmx = fmaxf(tmx, __shfl_xor_sync(0xffffffffu, tmx, o));
        tmn = fminf(tmn, __shfl_xor_sync(0xffffffffu, tmn, o));
    }
    __shared__ float smx[32], smn[32];
    int w = threadIdx.x >> 5, nw = blockDim.x >> 5;
    if ((threadIdx.x & 31) == 0) { smx[w] = tmx; smn[w] = tmn; }
    __syncthreads();
    if (threadIdx.x == 0) {
        for (int i = 1; i < nw; i++) { tmx = fmaxf(tmx, smx[i]); tmn = fminf(tmn, smn[i]); }
        atomicMax(gmax, __float_as_uint(fmaxf(tmx, 0.f)));
        atomicMax(gmin, __float_as_uint(fminf(tmn, 0.f)));
    }
}

// tiled-swizzled dst offset for element group (row, k..k+3) -> 8-byte slot
__device__ __forceinline__ size_t tiled_off(int row, int k) {
    int tile = row >> 8, r = row & 255, ks = k >> 6;
    int c16 = (k & 63) >> 3, half = (k >> 2) & 1;
    return ((((size_t)tile * (KDIM / 64) + ks) * 256 + r) << 7) +
           (size_t)(((c16 ^ (r & 7)) << 4) + (half << 3));
}

// FUSED: blocks [0, ODIM) quantize W rows; blocks [ODIM, ODIM+2048) reduce x min/max.
#define MMX_BLOCKS 2048
__global__ void quantw_minmax_kernel(const float* __restrict__ w,
                                     const float4* __restrict__ x4, int n4) {
    if (blockIdx.x >= ODIM) {
        int mb = blockIdx.x - ODIM;
        float tmx = 0.f, tmn = 0.f;
        for (int i = mb * blockDim.x + threadIdx.x; i < n4; i += MMX_BLOCKS * blockDim.x) {
            float4 v = x4[i];
            tmx = fmaxf(tmx, fmaxf(fmaxf(v.x, v.y), fmaxf(v.z, v.w)));
            tmn = fminf(tmn, fminf(fminf(v.x, v.y), fminf(v.z, v.w)));
        }
        block_minmax_atomic(tmn, tmx, &g_xmin_u, &g_xmax_u);
        return;
    }
    int row = blockIdx.x;
    const float4* wr = (const float4*)(w + (size_t)row * KDIM);
    float4 v[4];
    float am = 0.f;
    #pragma unroll
    for (int i = 0; i < 4; i++) {
        v[i] = wr[threadIdx.x + i * 256];
        am = fmaxf(am, fmaxf(fmaxf(fabsf(v[i].x), fabsf(v[i].y)),
                             fmaxf(fabsf(v[i].z), fabsf(v[i].w))));
    }
    #pragma unroll
    for (int o = 16; o > 0; o >>= 1) am = fmaxf(am, __shfl_xor_sync(0xffffffffu, am, o));
    __shared__ float sred[8];
    __shared__ float swsv;
    if ((threadIdx.x & 31) == 0) sred[threadIdx.x >> 5] = am;
    __syncthreads();
    if (threadIdx.x == 0) {
        for (int i = 1; i < 8; i++) am = fmaxf(am, sred[i]);
        float ws = am / 127.f;
        swsv = ws;
        g_wscale[row] = ws;
    }
    __syncthreads();
    float ws = swsv;
    #pragma unroll
    for (int i = 0; i < 4; i++) {
        int k = (threadIdx.x + i * 256) * 4;
        float q0 = fminf(fmaxf(rintf(v[i].x / ws), -127.f), 127.f);
        float q1 = fminf(fmaxf(rintf(v[i].y / ws), -127.f), 127.f);
        float q2 = fminf(fmaxf(rintf(v[i].z / ws), -127.f), 127.f);
        float q3 = fminf(fmaxf(rintf(v[i].w / ws), -127.f), 127.f);
        __nv_bfloat162 p0, p1;
        p0.x = __float2bfloat16_rn(q0); p0.y = __float2bfloat16_rn(q1);
        p1.x = __float2bfloat16_rn(q2); p1.y = __float2bfloat16_rn(q3);
        uint2 pk;
        pk.x = *(uint32_t*)&p0; pk.y = *(uint32_t*)&p1;
        *(uint2*)(g_qwt + tiled_off(row, k)) = pk;
    }
}

// params1: derive act-quant params; also reset r-minmax accumulators (consumed by
// GEMM's atomics later this execution) to maintain the zero-invariant.
__global__ void params1_kernel() {
    float mx = __uint_as_float(g_xmax_u);
    float mn = __uint_as_float(g_xmin_u);
    float sc = (mx - mn) / 255.f;
    g_sc = sc;
    g_zp = rintf(-128.f - mn / sc);
    g_rmax_u = 0u;
    g_rmin_u = 0u;
}

// activation quant: 8 elems/thread -> one 16B aligned tiled-layout write per thread
__global__ void quantx_kernel(const float4* __restrict__ x4, int n8) {
    float sc = g_sc, zp = g_zp;
    for (int i = blockIdx.x * blockDim.x + threadIdx.x; i < n8; i += gridDim.x * blockDim.x) {
        int e = i * 8;
        int row = e >> 12, k = e & (KDIM - 1);
        float4 a = x4[2 * i];
        float4 b = x4[2 * i + 1];
        float q0 = fminf(fmaxf(rintf(a.x / sc) + zp, -128.f), 127.f) - zp;
        float q1 = fminf(fmaxf(rintf(a.y / sc) + zp, -128.f), 127.f) - zp;
        float q2 = fminf(fmaxf(rintf(a.z / sc) + zp, -128.f), 127.f) - zp;
        float q3 = fminf(fmaxf(rintf(a.w / sc) + zp, -128.f), 127.f) - zp;
        float q4 = fminf(fmaxf(rintf(b.x / sc) + zp, -128.f), 127.f) - zp;
        float q5 = fminf(fmaxf(rintf(b.y / sc) + zp, -128.f), 127.f) - zp;
        float q6 = fminf(fmaxf(rintf(b.z / sc) + zp, -128.f), 127.f) - zp;
        float q7 = fminf(fmaxf(rintf(b.w / sc) + zp, -128.f), 127.f) - zp;
        __nv_bfloat162 p0, p1, p2, p3;
        p0.x = __float2bfloat16_rn(q0); p0.y = __float2bfloat16_rn(q1);
        p1.x = __float2bfloat16_rn(q2); p1.y = __float2bfloat16_rn(q3);
        p2.x = __float2bfloat16_rn(q4); p2.y = __float2bfloat16_rn(q5);
        p3.x = __float2bfloat16_rn(q6); p3.y = __float2bfloat16_rn(q7);
        uint4 pk;
        pk.x = *(uint32_t*)&p0; pk.y = *(uint32_t*)&p1;
        pk.z = *(uint32_t*)&p2; pk.w = *(uint32_t*)&p3;
        // k..k+7 fills both 8B halves of one swizzled 16B chunk -> 16B store
        int tile = row >> 8, r = row & 255, ks = k >> 6, c16 = (k & 63) >> 3;
        size_t off = ((((size_t)tile * (KDIM / 64) + ks) * 256 + r) << 7) +
                     (size_t)((c16 ^ (r & 7)) << 4);
        *(uint4*)(g_qxt + off) = pk;
    }
}

// ===== tcgen05 GEMM: 256x256 tile, BK=64 bf16, 3 stages, round-13 cp.async pipeline =====
#define STAGES 3
#define STAGE_BYTES 65536
#define SMEM_STAGE0 1024
#define SMEM_QB (SMEM_STAGE0 + STAGES * STAGE_BYTES)
#define GEMM_SMEM (SMEM_QB + 256 * 4)
#define NKITER (KDIM / 64)

#if HAS_TCGEN05
__device__ __forceinline__ void load_stage(uint32_t sbase, int k0, int by, int bx, int tid) {
    const unsigned char* Ag = g_qxt + ((size_t)by * NKITER + k0) * 32768;
    const unsigned char* Bg = g_qwt + ((size_t)bx * NKITER + k0) * 32768;
    #pragma unroll
    for (int i = 0; i < 8; i++) {
        uint32_t off = (uint32_t)(tid + i * 256) * 16;   // 0..32767, identity copy
        cp16(sbase + off,         Ag + off);
        cp16(sbase + 32768 + off, Bg + off);
    }
}
#endif

__global__ void __launch_bounds__(256, 1) gemm_tc_kernel(const float* __restrict__ bias,
                                                         float* __restrict__ out) {
#if HAS_TCGEN05
    extern __shared__ __align__(1024) char ds[];
    uint32_t sb = smem_u32(ds);
    int tid = threadIdx.x, wid = tid >> 5, lane = tid & 31;
    int bx = blockIdx.x, by = blockIdx.y;
    int bm = by * 256, bn = bx * 256;

    if (wid == 0) TCGEN05_ALLOC(sb + 0, 512);
    if (tid == 0) {
        #pragma unroll
        for (int s = 0; s < STAGES; s++) MBAR_INIT(sb + 8 + s * 8, 1);
    }
    __syncthreads();
    uint32_t tb;
    asm volatile("ld.shared.b32 %0, [%1];" : "=r"(tb) : "r"(sb));

    load_stage(sb + SMEM_STAGE0 + 0 * STAGE_BYTES, 0, by, bx, tid); CP_COMMIT();
    load_stage(sb + SMEM_STAGE0 + 1 * STAGE_BYTES, 1, by, bx, tid); CP_COMMIT();

    int ph0 = 0, ph1 = 0, ph2 = 0;
    for (int k0 = 0; k0 < NKITER; k0++) {
        int s = k0 % STAGES;
        CP_WAIT1();
        FENCE_PROXY_ASYNC();
        __syncthreads();                       // stage s visible to all

        if (tid == 0) {
            uint32_t stg = sb + SMEM_STAGE0 + s * STAGE_BYTES;
            uint64_t ab = make_desc(stg);
            uint64_t bb = make_desc(stg + 32768);
            #pragma unroll
            for (int atom = 0; atom < 2; atom++)
                #pragma unroll
                for (int kk = 0; kk < 4; kk++)
                    mma_f16_ss(tb + atom * 256, ab + atom * 1024 + kk * 2, bb + kk * 2,
                               GEMM_IDESC, !(k0 == 0 && kk == 0));
            TCGEN05_COMMIT(sb + 8 + s * 8);
        }

        int kl = k0 + STAGES - 1;
        if (kl < NKITER) {
            int t = kl % STAGES;
            if (k0 > 0) {                      // WAR: slot reused, wait MMA of iter k0-1
                int ph = (t == 0) ? ph0 : (t == 1) ? ph1 : ph2;
                MBAR_WAIT_PARITY(sb + 8 + t * 8, ph);
                if (t == 0) ph0 ^= 1; else if (t == 1) ph1 ^= 1; else ph2 ^= 1;
            }
            load_stage(sb + SMEM_STAGE0 + t * STAGE_BYTES, kl, by, bx, tid);
        }
        CP_COMMIT();                           // one group per iter (possibly empty)
    }

    {   // wait for last iteration's MMAs
        int sl = (NKITER - 1) % STAGES;
        int ph = (sl == 0) ? ph0 : (sl == 1) ? ph1 : ph2;
        MBAR_WAIT_PARITY(sb + 8 + sl * 8, ph);
    }
    TCGEN05_FENCE_AFTER();

    // per-column qbias
    float sc = g_sc;
    float* qb = (float*)(ds + SMEM_QB);
    {
        int col = bn + tid;
        qb[tid] = rintf(bias[col] / (g_wscale[col] * sc));
    }
    __syncthreads();

    int atom = wid >> 2;
    int row = bm + atom * 128 + (wid & 3) * 32 + lane;
    float tmx = 0.f, tmn = 0.f;
    float* orow = out + (size_t)row * ODIM + bn;
    #pragma unroll
    for (int ch = 0; ch < 8; ch++) {
        uint32_t dr[32];
        TCGEN05_LD_X32(dr, tb + atom * 256 + ch * 32);
        TCGEN05_WAIT_LD();
        float v[32];
        #pragma unroll
        for (int c = 0; c < 32; c++) {
            float f = __uint_as_float(dr[c]) + qb[ch * 32 + c];
            v[c] = f;
            tmx = fmaxf(tmx, f);
            tmn = fminf(tmn, f);
        }
        #pragma unroll
        for (int c = 0; c < 32; c += 4)
            *(float4*)&orow[ch * 32 + c] = make_float4(v[c], v[c + 1], v[c + 2], v[c + 3]);
    }
    TCGEN05_FENCE_BEFORE();
    block_minmax_atomic(tmn, tmx, &g_rmin_u, &g_rmax_u);
    __syncthreads();
    if (wid == 0) {
        TCGEN05_RELINQ();
        TCGEN05_DEALLOC(tb, 512);
    }
#endif
}

// params2: derive requant params; also reset x-minmax accumulators (already
// consumed by params1) so the zero-invariant holds for the next execution.
__global__ void params2_kernel() {
    float rmx = __uint_as_float(g_rmax_u);
    float rmn = __uint_as_float(g_rmin_u);
    float resc = (rmx - rmn) / 255.f;
    g_resc = resc;
    g_rezp = rintf(-128.f - rmn / resc);
    g_xmax_u = 0u;
    g_xmin_u = 0u;
}

__global__ void requant_kernel(float4* __restrict__ out4, int n4) {
    float resc = g_resc, rezp = g_rezp, sc = g_sc;
    for (int i = blockIdx.x * blockDim.x + threadIdx.x; i < n4; i += gridDim.x * blockDim.x) {
        float4 v = out4[i];
        int col = (i * 4) & (ODIM - 1);
        float s0 = (sc * g_wscale[col])     * resc;
        float s1 = (sc * g_wscale[col + 1]) * resc;
        float s2 = (sc * g_wscale[col + 2]) * resc;
        float s3 = (sc * g_wscale[col + 3]) * resc;
        float r0 = fminf(fmaxf(rintf(v.x / resc) + rezp, -128.f), 127.f);
        float r1 = fminf(fmaxf(rintf(v.y / resc) + rezp, -128.f), 127.f);
        float r2 = fminf(fmaxf(rintf(v.z / resc) + rezp, -128.f), 127.f);
        float r3 = fminf(fmaxf(rintf(v.w / resc) + rezp, -128.f), 127.f);
        v.x = (r0 - rezp) * s0;
        v.y = (r1 - rezp) * s1;
        v.z = (r2 - rezp) * s2;
        v.w = (r3 - rezp) * s3;
        out4[i] = v;
    }
}

// ---------------- launch ----------------
extern "C" void kernel_launch(void* const* d_in, const int* in_sizes, int n_in,
                              void* d_out, int out_size) {
    const float* x    = (const float*)d_in[0];
    const float* w    = (const float*)d_in[1];
    const float* bias = (const float*)d_in[2];
    float* out = (float*)d_out;

    cudaFuncSetAttribute(gemm_tc_kernel, cudaFuncAttributeMaxDynamicSharedMemorySize, GEMM_SMEM);

    quantw_minmax_kernel<<<ODIM + MMX_BLOCKS, 256>>>(w, (const float4*)x, NROWS * KDIM / 4);
    params1_kernel<<<1, 1>>>();
    quantx_kernel<<<8192, 256>>>((const float4*)x, NROWS * KDIM / 8);

    dim3 grid_tc(ODIM / 256, NROWS / 256);
    gemm_tc_kernel<<<grid_tc, 256, GEMM_SMEM>>>(bias, out);

    params2_kernel<<<1, 1>>>();
    requant_kernel<<<12288, 256>>>((float4*)out, NROWS * ODIM / 4);
}

// round 17
// speedup vs baseline: 1.0314x; 1.0314x over previous
#include <cuda_runtime.h>
#include <cuda_bf16.h>
#include <cstdint>

#define NROWS 16384
#define KDIM  4096
#define ODIM  4096

// Arch-feature guard: tcgen05 only exists in arch-specific ('a') / family targets.
#if defined(__CUDA_ARCH_FEAT_SM103_ALL) || defined(__CUDA_ARCH_FEAT_SM100_ALL) || \
    defined(__CUDA_ARCH_SPECIFIC__) || defined(__CUDA_ARCH_FAMILY_SPECIFIC__)
#define HAS_TCGEN05 1
#else
#define HAS_TCGEN05 0
#endif

// ---------------- scratch: TILED-SWIZZLED bf16 operands ----------------
__device__ unsigned char g_qxt[(size_t)NROWS * KDIM * 2];   // 128 MB
__device__ unsigned char g_qwt[(size_t)ODIM * KDIM * 2];    // 32 MB
__device__ float g_wscale[ODIM];
// Zero-invariant state: zero at module load; params1 resets r-minmax, params2
// resets x-minmax, so every execution restores the invariant.
__device__ unsigned int g_xmax_u, g_xmin_u, g_rmax_u, g_rmin_u;
__device__ float g_sc, g_zp, g_resc, g_rezp;

// ---------------- PTX helpers ----------------
__device__ __forceinline__ uint32_t smem_u32(const void* p) {
    uint32_t a;
    asm("{ .reg .u64 t; cvta.to.shared.u64 t, %1; cvt.u32.u64 %0, t; }" : "=r"(a) : "l"(p));
    return a;
}
#define TCGEN05_ALLOC(sm, n) \
    asm volatile("tcgen05.alloc.cta_group::1.sync.aligned.shared::cta.b32 [%0], %1;" \
                 :: "r"((uint32_t)(sm)), "r"((uint32_t)(n)) : "memory")
#define TCGEN05_DEALLOC(t, n) \
    asm volatile("tcgen05.dealloc.cta_group::1.sync.aligned.b32 %0, %1;" :: "r"(t), "r"((uint32_t)(n)))
#define TCGEN05_RELINQ() \
    asm volatile("tcgen05.relinquish_alloc_permit.cta_group::1.sync.aligned;")
#define TCGEN05_COMMIT(mb) \
    asm volatile("tcgen05.commit.cta_group::1.mbarrier::arrive::one.shared::cluster.b64 [%0];" \
                 :: "r"((uint32_t)(mb)) : "memory")
#define TCGEN05_FENCE_AFTER()  asm volatile("tcgen05.fence::after_thread_sync;" ::: "memory")
#define TCGEN05_FENCE_BEFORE() asm volatile("tcgen05.fence::before_thread_sync;" ::: "memory")
#define TCGEN05_WAIT_LD()      asm volatile("tcgen05.wait::ld.sync.aligned;" ::: "memory")
#define MBAR_INIT(a, c) \
    asm volatile("mbarrier.init.shared.b64 [%0], %1;" :: "r"((uint32_t)(a)), "r"((uint32_t)(c)) : "memory")
#define MBAR_ARRIVE(a) \
    asm volatile("mbarrier.arrive.shared.b64 _, [%0];" :: "r"((uint32_t)(a)) : "memory")
#define FENCE_PROXY_ASYNC() asm volatile("fence.proxy.async.shared::cta;" ::: "memory")

#define MBAR_WAIT_PARITY(mb, par) do {                                            \
    uint32_t _m = (uint32_t)(mb); uint32_t _p = (uint32_t)(par);                  \
    asm volatile(                                                                 \
        "{\n\t.reg .pred P1;\n\t"                                                 \
        "WL_%=:\n\t"                                                              \
        "mbarrier.try_wait.parity.acquire.cta.shared::cta.b64 P1, [%0], %1, 0x989680;\n\t" \
        "@P1 bra.uni WD_%=;\n\t"                                                  \
        "bra.uni WL_%=;\n\t"                                                      \
        "WD_%=:\n\t}"                                                             \
        :: "r"(_m), "r"(_p) : "memory");                                          \
} while (0)

#define TCGEN05_LD_X32(r, addr) \
    asm volatile( \
        "tcgen05.ld.sync.aligned.32x32b.x32.b32 " \
        "{%0, %1, %2, %3, %4, %5, %6, %7, " \
        " %8, %9, %10, %11, %12, %13, %14, %15, " \
        " %16, %17, %18, %19, %20, %21, %22, %23, " \
        " %24, %25, %26, %27, %28, %29, %30, %31}, [%32];" \
        : "=r"((r)[0]),  "=r"((r)[1]),  "=r"((r)[2]),  "=r"((r)[3]), \
          "=r"((r)[4]),  "=r"((r)[5]),  "=r"((r)[6]),  "=r"((r)[7]), \
          "=r"((r)[8]),  "=r"((r)[9]),  "=r"((r)[10]), "=r"((r)[11]), \
          "=r"((r)[12]), "=r"((r)[13]), "=r"((r)[14]), "=r"((r)[15]), \
          "=r"((r)[16]), "=r"((r)[17]), "=r"((r)[18]), "=r"((r)[19]), \
          "=r"((r)[20]), "=r"((r)[21]), "=r"((r)[22]), "=r"((r)[23]), \
          "=r"((r)[24]), "=r"((r)[25]), "=r"((r)[26]), "=r"((r)[27]), \
          "=r"((r)[28]), "=r"((r)[29]), "=r"((r)[30]), "=r"((r)[31]) \
        : "r"(addr))

__device__ __forceinline__ void cp16(uint32_t s, const void* g) {
    asm volatile("cp.async.cg.shared.global [%0], [%1], 16;" :: "r"(s), "l"(g));
}
#define CP_COMMIT() asm volatile("cp.async.commit_group;" ::: "memory")
#define CP_WAIT1()  asm volatile("cp.async.wait_group 1;" ::: "memory")
#define CP_WAIT0()  asm volatile("cp.async.wait_group 0;" ::: "memory")

// SW128 K-major descriptor (layout=2, version=1, SBO=64, LBO=1) — 128B rows
__device__ __forceinline__ uint64_t make_desc(uint32_t addr) {
    return ((uint64_t)2 << 61) | ((uint64_t)1 << 46) | ((uint64_t)64 << 32) |
           ((uint64_t)1 << 16) | ((addr >> 4) & 0x3FFF);
}

// idesc kind::f16: dtype=F32(bit4), atype=BF16(bit7), btype=BF16(bit10), N=256, M=128
#define GEMM_IDESC ((1u << 4) | (1u << 7) | (1u << 10) | ((256u / 8) << 17) | ((128u / 16) << 24))

__device__ __forceinline__ void mma_f16_ss(uint32_t d, uint64_t ad, uint64_t bd,
                                           uint32_t idesc, bool acc) {
    uint32_t e = acc ? 1u : 0u;
    asm volatile(
        "{\n\t.reg .pred p;\n\t"
        "setp.ne.u32 p, %4, 0;\n\t"
        "tcgen05.mma.cta_group::1.kind::f16 [%0], %1, %2, %3, {%5,%5,%5,%5}, p;\n\t"
        "}"
        :: "r"(d), "l"(ad), "l"(bd), "r"(idesc), "r"(e), "r"(0u) : "memory");
}

// ---------------- misc kernels ----------------
__device__ __forceinline__ void block_minmax_atomic(float tmn, float tmx,
                                                    unsigned int* gmin, unsigned int* gmax) {
    #pragma unroll
    for (int o = 16; o > 0; o >>= 1) {
        tmx = fmaxf(tmx, __shfl_xor_sync(0xffffffffu, tmx, o));
        tmn = fminf(tmn, __shfl_xor_sync(0xffffffffu, tmn, o));
    }
    __shared__ float smx[32], smn[32];
    int w = threadIdx.x >> 5, nw = (blockDim.x + 31) >> 5;
    if ((threadIdx.x & 31) == 0) { smx[w] = tmx; smn[w] = tmn; }
    __syncthreads();
    if (threadIdx.x == 0) {
        for (int i = 1; i < nw; i++) { tmx = fmaxf(tmx, smx[i]); tmn = fminf(tmn, smn[i]); }
        atomicMax(gmax, __float_as_uint(fmaxf(tmx, 0.f)));
        atomicMax(gmin, __float_as_uint(fminf(tmn, 0.f)));
    }
}

// tiled-swizzled dst offset for element group (row, k..k+3) -> 8-byte slot
__device__ __forceinline__ size_t tiled_off(int row, int k) {
    int tile = row >> 8, r = row & 255, ks = k >> 6;
    int c16 = (k & 63) >> 3, half = (k >> 2) & 1;
    return ((((size_t)tile * (KDIM / 64) + ks) * 256 + r) << 7) +
           (size_t)(((c16 ^ (r & 7)) << 4) + (half << 3));
}

// FUSED: blocks [0, ODIM) quantize W rows; blocks [ODIM, ODIM+2048) reduce x min/max.
#define MMX_BLOCKS 2048
__global__ void quantw_minmax_kernel(const float* __restrict__ w,
                                     const float4* __restrict__ x4, int n4) {
    if (blockIdx.x >= ODIM) {
        int mb = blockIdx.x - ODIM;
        float tmx = 0.f, tmn = 0.f;
        for (int i = mb * blockDim.x + threadIdx.x; i < n4; i += MMX_BLOCKS * blockDim.x) {
            float4 v = x4[i];
            tmx = fmaxf(tmx, fmaxf(fmaxf(v.x, v.y), fmaxf(v.z, v.w)));
            tmn = fminf(tmn, fminf(fminf(v.x, v.y), fminf(v.z, v.w)));
        }
        block_minmax_atomic(tmn, tmx, &g_xmin_u, &g_xmax_u);
        return;
    }
    int row = blockIdx.x;
    const float4* wr = (const float4*)(w + (size_t)row * KDIM);
    float4 v[4];
    float am = 0.f;
    #pragma unroll
    for (int i = 0; i < 4; i++) {
        v[i] = wr[threadIdx.x + i * 256];
        am = fmaxf(am, fmaxf(fmaxf(fabsf(v[i].x), fabsf(v[i].y)),
                             fmaxf(fabsf(v[i].z), fabsf(v[i].w))));
    }
    #pragma unroll
    for (int o = 16; o > 0; o >>= 1) am = fmaxf(am, __shfl_xor_sync(0xffffffffu, am, o));
    __shared__ float sred[8];
    __shared__ float swsv;
    if ((threadIdx.x & 31) == 0) sred[threadIdx.x >> 5] = am;
    __syncthreads();
    if (threadIdx.x == 0) {
        for (int i = 1; i < 8; i++) am = fmaxf(am, sred[i]);
        float ws = am / 127.f;
        swsv = ws;
        g_wscale[row] = ws;
    }
    __syncthreads();
    float ws = swsv;
    #pragma unroll
    for (int i = 0; i < 4; i++) {
        int k = (threadIdx.x + i * 256) * 4;
        float q0 = fminf(fmaxf(rintf(v[i].x / ws), -127.f), 127.f);
        float q1 = fminf(fmaxf(rintf(v[i].y / ws), -127.f), 127.f);
        float q2 = fminf(fmaxf(rintf(v[i].z / ws), -127.f), 127.f);
        float q3 = fminf(fmaxf(rintf(v[i].w / ws), -127.f), 127.f);
        __nv_bfloat162 p0, p1;
        p0.x = __float2bfloat16_rn(q0); p0.y = __float2bfloat16_rn(q1);
        p1.x = __float2bfloat16_rn(q2); p1.y = __float2bfloat16_rn(q3);
        uint2 pk;
        pk.x = *(uint32_t*)&p0; pk.y = *(uint32_t*)&p1;
        *(uint2*)(g_qwt + tiled_off(row, k)) = pk;
    }
}

__global__ void params1_kernel() {
    float mx = __uint_as_float(g_xmax_u);
    float mn = __uint_as_float(g_xmin_u);
    float sc = (mx - mn) / 255.f;
    g_sc = sc;
    g_zp = rintf(-128.f - mn / sc);
    g_rmax_u = 0u;
    g_rmin_u = 0u;
}

// activation quant: 8 elems/thread -> one 16B aligned tiled-layout write per thread
__global__ void quantx_kernel(const float4* __restrict__ x4, int n8) {
    float sc = g_sc, zp = g_zp;
    for (int i = blockIdx.x * blockDim.x + threadIdx.x; i < n8; i += gridDim.x * blockDim.x) {
        int e = i * 8;
        int row = e >> 12, k = e & (KDIM - 1);
        float4 a = x4[2 * i];
        float4 b = x4[2 * i + 1];
        float q0 = fminf(fmaxf(rintf(a.x / sc) + zp, -128.f), 127.f) - zp;
        float q1 = fminf(fmaxf(rintf(a.y / sc) + zp, -128.f), 127.f) - zp;
        float q2 = fminf(fmaxf(rintf(a.z / sc) + zp, -128.f), 127.f) - zp;
        float q3 = fminf(fmaxf(rintf(a.w / sc) + zp, -128.f), 127.f) - zp;
        float q4 = fminf(fmaxf(rintf(b.x / sc) + zp, -128.f), 127.f) - zp;
        float q5 = fminf(fmaxf(rintf(b.y / sc) + zp, -128.f), 127.f) - zp;
        float q6 = fminf(fmaxf(rintf(b.z / sc) + zp, -128.f), 127.f) - zp;
        float q7 = fminf(fmaxf(rintf(b.w / sc) + zp, -128.f), 127.f) - zp;
        __nv_bfloat162 p0, p1, p2, p3;
        p0.x = __float2bfloat16_rn(q0); p0.y = __float2bfloat16_rn(q1);
        p1.x = __float2bfloat16_rn(q2); p1.y = __float2bfloat16_rn(q3);
        p2.x = __float2bfloat16_rn(q4); p2.y = __float2bfloat16_rn(q5);
        p3.x = __float2bfloat16_rn(q6); p3.y = __float2bfloat16_rn(q7);
        uint4 pk;
        pk.x = *(uint32_t*)&p0; pk.y = *(uint32_t*)&p1;
        pk.z = *(uint32_t*)&p2; pk.w = *(uint32_t*)&p3;
        int tile = row >> 8, r = row & 255, ks = k >> 6, c16 = (k & 63) >> 3;
        size_t off = ((((size_t)tile * (KDIM / 64) + ks) * 256 + r) << 7) +
                     (size_t)((c16 ^ (r & 7)) << 4);
        *(uint4*)(g_qxt + off) = pk;
    }
}

// ===== tcgen05 GEMM: 256x256 tile, BK=64, 3 stages, WARP-SPECIALIZED =====
// 288 threads: warp 0 = MMA driver (tid 0 active in loop); warps 1-8 = 256 loaders.
// full[s]: count=256, loaders arrive after their stage-s cp.async group lands.
// empty[s]: count=1, driver's tcgen05.commit (MMA done with slot s).
#define STAGES 3
#define STAGE_BYTES 65536
#define SMEM_STAGE0 1024
#define SMEM_FULLB 8
#define SMEM_EMPTYB 32
#define SMEM_QB (SMEM_STAGE0 + STAGES * STAGE_BYTES)
#define GEMM_SMEM (SMEM_QB + 256 * 4)
#define NKITER (KDIM / 64)

#if HAS_TCGEN05
__device__ __forceinline__ void load_stage(uint32_t sbase, int k0, int by, int bx, int ltid) {
    const unsigned char* Ag = g_qxt + ((size_t)by * NKITER + k0) * 32768;
    const unsigned char* Bg = g_qwt + ((size_t)bx * NKITER + k0) * 32768;
    #pragma unroll
    for (int i = 0; i < 8; i++) {
        uint32_t off = (uint32_t)(ltid + i * 256) * 16;   // 0..32767, identity copy
        cp16(sbase + off,         Ag + off);
        cp16(sbase + 32768 + off, Bg + off);
    }
}
#endif

__global__ void __launch_bounds__(288, 1) gemm_tc_kernel(const float* __restrict__ bias,
                                                         float* __restrict__ out) {
#if HAS_TCGEN05
    extern __shared__ __align__(1024) char ds[];
    uint32_t sb = smem_u32(ds);
    int tid = threadIdx.x, wid = tid >> 5, lane = tid & 31;
    int bx = blockIdx.x, by = blockIdx.y;
    int bm = by * 256, bn = bx * 256;

    if (wid == 0) TCGEN05_ALLOC(sb + 0, 512);
    if (tid == 0) {
        #pragma unroll
        for (int s = 0; s < STAGES; s++) {
            MBAR_INIT(sb + SMEM_FULLB + s * 8, 256);   // 256 loader arrivals
            MBAR_INIT(sb + SMEM_EMPTYB + s * 8, 1);    // driver's commit
        }
    }
    __syncthreads();
    uint32_t tb;
    asm volatile("ld.shared.b32 %0, [%1];" : "=r"(tb) : "r"(sb));

    if (wid == 0) {
        // ---- MMA driver ----
        if (tid == 0) {
            int f0 = 0, f1 = 0, f2 = 0;
            for (int k0 = 0; k0 < NKITER; k0++) {
                int s = k0 % STAGES;
                uint32_t stg = sb + SMEM_STAGE0 + s * STAGE_BYTES;
                uint32_t fb = sb + SMEM_FULLB + s * 8;
                int fp = (s == 0) ? f0 : (s == 1) ? f1 : f2;
                MBAR_WAIT_PARITY(fb, fp);
                if (s == 0) f0 ^= 1; else if (s == 1) f1 ^= 1; else f2 ^= 1;

                uint64_t ab = make_desc(stg);
                uint64_t bb = make_desc(stg + 32768);
                #pragma unroll
                for (int atom = 0; atom < 2; atom++)
                    #pragma unroll
                    for (int kk = 0; kk < 4; kk++)
                        mma_f16_ss(tb + atom * 256, ab + atom * 1024 + kk * 2, bb + kk * 2,
                                   GEMM_IDESC, !(k0 == 0 && kk == 0));
                TCGEN05_COMMIT(sb + SMEM_EMPTYB + s * 8);
            }
            // wait completion of the final slot's last commit:
            // slot sl completed uses = #k in [0,NKITER) with k%3==sl; parity of the
            // last completion = (uses-1)&1.
            int sl = (NKITER - 1) % STAGES;
            int uses = (NKITER - 1 - sl) / STAGES + 1;
            MBAR_WAIT_PARITY(sb + SMEM_EMPTYB + sl * 8, (uses - 1) & 1);
        }
    } else {
        // ---- loaders (256 threads) ----
        int ltid = tid - 32;
        int e0 = 0, e1 = 0, e2 = 0;
        for (int j = 0; j < NKITER; j++) {
            int s = j % STAGES;
            uint32_t stg = sb + SMEM_STAGE0 + s * STAGE_BYTES;
            if (j >= STAGES) {                 // slot reused: MMA j-3 must be done
                uint32_t eb = sb + SMEM_EMPTYB + s * 8;
                int ep = (s == 0) ? e0 : (s == 1) ? e1 : e2;
                MBAR_WAIT_PARITY(eb, ep);
                if (s == 0) e0 ^= 1; else if (s == 1) e1 ^= 1; else e2 ^= 1;
            }
            load_stage(stg, j, by, bx, ltid);
            CP_COMMIT();
            if (j >= 1) {                      // group j-1 landed -> publish stage j-1
                CP_WAIT1();
                FENCE_PROXY_ASYNC();
                MBAR_ARRIVE(sb + SMEM_FULLB + ((j - 1) % STAGES) * 8);
            }
        }
        CP_WAIT0();
        FENCE_PROXY_ASYNC();
        MBAR_ARRIVE(sb + SMEM_FULLB + ((NKITER - 1) % STAGES) * 8);
    }

    __syncthreads();
    TCGEN05_FENCE_AFTER();

    // per-column qbias (first 256 threads)
    float sc = g_sc;
    float* qb = (float*)(ds + SMEM_QB);
    if (tid < 256) {
        int col = bn + tid;
        qb[tid] = rintf(bias[col] / (g_wscale[col] * sc));
    }
    __syncthreads();

    // epilogue: warps 0-7 read TMEM; warp 8 contributes neutral min/max
    float tmx = 0.f, tmn = 0.f;
    if (wid < 8) {
        int atom = wid >> 2;
        int row = bm + atom * 128 + (wid & 3) * 32 + lane;
        float* orow = out + (size_t)row * ODIM + bn;
        #pragma unroll
        for (int ch = 0; ch < 8; ch++) {
            uint32_t dr[32];
            TCGEN05_LD_X32(dr, tb + atom * 256 + ch * 32);
            TCGEN05_WAIT_LD();
            float v[32];
            #pragma unroll
            for (int c = 0; c < 32; c++) {
                float f = __uint_as_float(dr[c]) + qb[ch * 32 + c];
                v[c] = f;
                tmx = fmaxf(tmx, f);
                tmn = fminf(tmn, f);
            }
            #pragma unroll
            for (int c = 0; c < 32; c += 4)
                *(float4*)&orow[ch * 32 + c] = make_float4(v[c], v[c + 1], v[c + 2], v[c + 3]);
        }
        TCGEN05_FENCE_BEFORE();
    }
    block_minmax_atomic(tmn, tmx, &g_rmin_u, &g_rmax_u);
    __syncthreads();
    if (wid == 0) {
        TCGEN05_RELINQ();
        TCGEN05_DEALLOC(tb, 512);
    }
#endif
}

__global__ void params2_kernel() {
    float rmx = __uint_as_float(g_rmax_u);
    float rmn = __uint_as_float(g_rmin_u);
    float resc = (rmx - rmn) / 255.f;
    g_resc = resc;
    g_rezp = rintf(-128.f - rmn / resc);
    g_xmax_u = 0u;
    g_xmin_u = 0u;
}

__global__ void requant_kernel(float4* __restrict__ out4, int n4) {
    float resc = g_resc, rezp = g_rezp, sc = g_sc;
    for (int i = blockIdx.x * blockDim.x + threadIdx.x; i < n4; i += gridDim.x * blockDim.x) {
        float4 v = out4[i];
        int col = (i * 4) & (ODIM - 1);
        float s0 = (sc * g_wscale[col])     * resc;
        float s1 = (sc * g_wscale[col + 1]) * resc;
        float s2 = (sc * g_wscale[col + 2]) * resc;
        float s3 = (sc * g_wscale[col + 3]) * resc;
        float r0 = fminf(fmaxf(rintf(v.x / resc) + rezp, -128.f), 127.f);
        float r1 = fminf(fmaxf(rintf(v.y / resc) + rezp, -128.f), 127.f);
        float r2 = fminf(fmaxf(rintf(v.z / resc) + rezp, -128.f), 127.f);
        float r3 = fminf(fmaxf(rintf(v.w / resc) + rezp, -128.f), 127.f);
        v.x = (r0 - rezp) * s0;
        v.y = (r1 - rezp) * s1;
        v.z = (r2 - rezp) * s2;
        v.w = (r3 - rezp) * s3;
        out4[i] = v;
    }
}

// ---------------- launch ----------------
extern "C" void kernel_launch(void* const* d_in, const int* in_sizes, int n_in,
                              void* d_out, int out_size) {
    const float* x    = (const float*)d_in[0];
    const float* w    = (const float*)d_in[1];
    const float* bias = (const float*)d_in[2];
    float* out = (float*)d_out;

    cudaFuncSetAttribute(gemm_tc_kernel, cudaFuncAttributeMaxDynamicSharedMemorySize, GEMM_SMEM);

    quantw_minmax_kernel<<<ODIM + MMX_BLOCKS, 256>>>(w, (const float4*)x, NROWS * KDIM / 4);
    params1_kernel<<<1, 1>>>();
    quantx_kernel<<<4096, 256>>>((const float4*)x, NROWS * KDIM / 8);

    dim3 grid_tc(ODIM / 256, NROWS / 256);
    gemm_tc_kernel<<<grid_tc, 288, GEMM_SMEM>>>(bias, out);

    params2_kernel<<<1, 1>>>();
    requant_kernel<<<8192, 256>>>((float4*)out, NROWS * ODIM / 4);
}